// round 8
// baseline (speedup 1.0000x reference)
#include <cuda_runtime.h>

// Swin window attention, fused per-window kernel, v6:
// v5 + bulk smem staging of qkv_w / proj_w (double-buffered, coalesced LDG.128).
// B=32, nW=64 -> 2048 windows; N=49 tokens, C=128, H=4 heads, hd=32.

#define NWIN 64
#define NTOK 49
#define CDIM 128
#define NHEAD 4
#define HDIM 32
#define TPB 512
#define QPITCH 130

using u64 = unsigned long long;

__device__ __forceinline__ void fma2(u64& d, u64 a, u64 b) {
    asm("fma.rn.f32x2 %0, %1, %2, %0;" : "+l"(d) : "l"(a), "l"(b));
}
__device__ __forceinline__ u64 pack2(float lo, float hi) {
    u64 r; asm("mov.b64 %0, {%1, %2};" : "=l"(r) : "f"(lo), "f"(hi)); return r;
}
__device__ __forceinline__ float2 unpack2(u64 v) {
    float2 r; asm("mov.b64 {%0, %1}, %2;" : "=f"(r.x), "=f"(r.y) : "l"(v)); return r;
}

// shared memory layout (floats)
static constexpr int OFF_XT   = 0;                       // [128][52]; later s_o [49][128]
static constexpr int OFF_Q    = OFF_XT + 128 * 52;       // 6656, [49][130]
static constexpr int OFF_KT   = 13028;                   // [128][52] (16B aligned)
static constexpr int OFF_V    = OFF_KT + 128 * 52;       // 19684, [49][128]
static constexpr int OFF_ATTN = OFF_V + NTOK * CDIM;     // 25956, [196][52]
static constexpr int OFF_REL  = OFF_ATTN + (NHEAD * NTOK) * 52;  // 36148, 169*4
static constexpr int OFF_MASK = OFF_REL + 169 * NHEAD;   // 36824, 49*49
static constexpr int OFF_W    = 39228;                   // 16B aligned; [2][16*384] = 12288
static constexpr int SMEM_FLOATS = OFF_W + 2 * 16 * 384; // 51516
static constexpr int SMEM_BYTES  = SMEM_FLOATS * 4;      // 206064

__global__ __launch_bounds__(TPB, 1)
void swin_window_attn_kernel(const float* __restrict__ x_all,
                             const float* __restrict__ mask,
                             const float* __restrict__ qkv_w,
                             const float* __restrict__ qkv_b,
                             const float* __restrict__ proj_w,
                             const float* __restrict__ proj_b,
                             const float* __restrict__ rel_table,
                             float* __restrict__ out)
{
    extern __shared__ float sm[];
    float* s_xT   = sm + OFF_XT;     // [128][52]
    float* s_q    = sm + OFF_Q;      // [49][130]
    float* s_kT   = sm + OFF_KT;     // [128][52]
    float* s_v    = sm + OFF_V;      // [49][128]
    float* s_attn = sm + OFF_ATTN;   // [196][52]
    float* s_rel  = sm + OFF_REL;    // [169][4]
    float* s_mask = sm + OFF_MASK;   // [49][49]
    float* s_w    = sm + OFF_W;      // weight staging, [2][6144] (P1) / [2][4096] (P5)
    float* s_o    = sm + OFF_XT;     // alias: x dead after phase 1

    const int tid = threadIdx.x;
    const int blk = blockIdx.x;
    const float* x  = x_all + (size_t)blk * (NTOK * CDIM);
    const float* mw = mask  + (size_t)(blk & (NWIN - 1)) * (NTOK * NTOK);

    // ---- stage x (transposed), rel_table, mask, qkv_w chunk 0 into smem ----
    for (int idx = tid; idx < NTOK * CDIM; idx += TPB) {
        const int r = idx >> 7;
        const int k = idx & 127;
        s_xT[k * 52 + r] = x[idx];
    }
    for (int idx = tid; idx < 169 * NHEAD; idx += TPB) s_rel[idx] = __ldg(&rel_table[idx]);
    for (int idx = tid; idx < NTOK * NTOK; idx += TPB) s_mask[idx] = __ldg(&mw[idx]);
    {
        const float4* src = reinterpret_cast<const float4*>(qkv_w);
        float4* dst = reinterpret_cast<float4*>(s_w);
        #pragma unroll
        for (int s = 0; s < 3; ++s) dst[tid + 512 * s] = src[tid + 512 * s];
    }
    __syncthreads();

    const int col   = tid & 127;
    const int g     = tid >> 7;       // 0..3
    const int rbase = g * 12;         // 0,12,24,36
    const int rcnt  = (g == 3) ? 13 : 12;

    // ---- phase 1: QKV GEMM, f32x2, smem-staged weights (8 chunks of 16 k) ----
    {
        u64 a0[6], a1[6], a2[6];
        float s0 = 0.f, s1 = 0.f, s2 = 0.f;
        #pragma unroll
        for (int p = 0; p < 6; ++p) { a0[p] = 0ull; a1[p] = 0ull; a2[p] = 0ull; }

        #pragma unroll 1
        for (int c = 0; c < 8; ++c) {
            // prefetch next chunk into registers (bulk coalesced, fully overlapped)
            float4 pf0, pf1, pf2;
            {
                const int cn = (c < 7) ? c + 1 : 7;
                const float4* src = reinterpret_cast<const float4*>(qkv_w + (size_t)cn * 16 * 384);
                pf0 = src[tid];
                pf1 = src[tid + 512];
                pf2 = src[tid + 1024];
            }
            // compute current chunk from smem
            const float* wb = s_w + (c & 1) * 6144;
            #pragma unroll
            for (int t = 0; t < 16; ++t) {
                const int kk = c * 16 + t;
                const float w0 = wb[t * 384 + col];
                const float w1 = wb[t * 384 + 128 + col];
                const float w2 = wb[t * 384 + 256 + col];
                const u64 w0p = pack2(w0, w0);
                const u64 w1p = pack2(w1, w1);
                const u64 w2p = pack2(w2, w2);
                const ulonglong2* xr = reinterpret_cast<const ulonglong2*>(&s_xT[kk * 52 + rbase]);
                const ulonglong2 p01 = xr[0];
                const ulonglong2 p23 = xr[1];
                const ulonglong2 p45 = xr[2];
                const float x12 = s_xT[kk * 52 + rbase + 12];
                fma2(a0[0], p01.x, w0p); fma2(a0[1], p01.y, w0p);
                fma2(a0[2], p23.x, w0p); fma2(a0[3], p23.y, w0p);
                fma2(a0[4], p45.x, w0p); fma2(a0[5], p45.y, w0p);
                fma2(a1[0], p01.x, w1p); fma2(a1[1], p01.y, w1p);
                fma2(a1[2], p23.x, w1p); fma2(a1[3], p23.y, w1p);
                fma2(a1[4], p45.x, w1p); fma2(a1[5], p45.y, w1p);
                fma2(a2[0], p01.x, w2p); fma2(a2[1], p01.y, w2p);
                fma2(a2[2], p23.x, w2p); fma2(a2[3], p23.y, w2p);
                fma2(a2[4], p45.x, w2p); fma2(a2[5], p45.y, w2p);
                s0 += x12 * w0;  s1 += x12 * w1;  s2 += x12 * w2;
            }
            // commit prefetched chunk into the other buffer
            {
                float4* dst = reinterpret_cast<float4*>(s_w + ((c + 1) & 1) * 6144);
                dst[tid]        = pf0;
                dst[tid + 512]  = pf1;
                dst[tid + 1024] = pf2;
            }
            __syncthreads();
        }

        const float b0 = __ldg(&qkv_b[col]);
        const float b1 = __ldg(&qkv_b[128 + col]);
        const float b2 = __ldg(&qkv_b[256 + col]);
        #pragma unroll
        for (int p = 0; p < 6; ++p) {
            const int r = rbase + 2 * p;
            const float2 f0 = unpack2(a0[p]);
            const float2 f1 = unpack2(a1[p]);
            const float2 f2 = unpack2(a2[p]);
            s_q[r * QPITCH + col]       = f0.x + b0;
            s_q[(r + 1) * QPITCH + col] = f0.y + b0;
            s_kT[col * 52 + r]          = f1.x + b1;
            s_kT[col * 52 + r + 1]      = f1.y + b1;
            s_v[r * 128 + col]          = f2.x + b2;
            s_v[(r + 1) * 128 + col]    = f2.y + b2;
        }
        if (rcnt == 13) {
            const int r = rbase + 12;
            s_q[r * QPITCH + col] = s0 + b0;
            s_kT[col * 52 + r]    = s1 + b1;
            s_v[r * 128 + col]    = s2 + b2;
        }
    }
    __syncthreads();

    // ---- phase 2: scores + bias + mask; thread = (h, row-pair, 4 adjacent j) ----
    {
        const float scale = 0.17677669529663687f;   // 1/sqrt(32)
        for (int u = tid; u < NHEAD * 25 * 13; u += TPB) {
            const int h   = u / (25 * 13);
            const int rem = u - h * (25 * 13);
            const int ib  = rem / 13;
            const int jg  = rem - ib * 13;
            const int j4  = jg * 4;
            const int i0  = ib;
            const bool has1 = (ib < 24);
            const int i1  = has1 ? ib + 25 : ib;

            const float* q0 = &s_q[i0 * QPITCH + h * HDIM];
            const float* q1 = &s_q[i1 * QPITCH + h * HDIM];
            const float* kc = &s_kT[(h * HDIM) * 52 + j4];

            u64 acc0a = 0ull, acc0b = 0ull, acc1a = 0ull, acc1b = 0ull;
            #pragma unroll
            for (int d = 0; d < HDIM; ++d) {
                const ulonglong2 kv = *reinterpret_cast<const ulonglong2*>(&kc[d * 52]);
                const float qv0 = q0[d];
                const float qv1 = q1[d];
                const u64 q0p = pack2(qv0, qv0);
                const u64 q1p = pack2(qv1, qv1);
                fma2(acc0a, kv.x, q0p); fma2(acc0b, kv.y, q0p);
                fma2(acc1a, kv.x, q1p); fma2(acc1b, kv.y, q1p);
            }
            const float2 r0a = unpack2(acc0a), r0b = unpack2(acc0b);
            const float2 r1a = unpack2(acc1a), r1b = unpack2(acc1b);
            float sv0[4] = {r0a.x, r0a.y, r0b.x, r0b.y};
            float sv1[4] = {r1a.x, r1a.y, r1b.x, r1b.y};

            const int yi0 = i0 / 7, xi0 = i0 - yi0 * 7;
            const int yi1 = i1 / 7, xi1 = i1 - yi1 * 7;
            float* arow0 = &s_attn[(h * NTOK + i0) * 52];
            float* arow1 = &s_attn[(h * NTOK + i1) * 52];
            const float* mrow0 = &s_mask[i0 * NTOK];
            const float* mrow1 = &s_mask[i1 * NTOK];
            #pragma unroll
            for (int jj = 0; jj < 4; ++jj) {
                const int j = j4 + jj;
                if (j < NTOK) {
                    const int yj = j / 7, xj = j - yj * 7;
                    const int r0 = (yi0 - yj + 6) * 13 + (xi0 - xj + 6);
                    arow0[j] = sv0[jj] * scale + s_rel[r0 * NHEAD + h] + mrow0[j];
                    if (has1) {
                        const int r1 = (yi1 - yj + 6) * 13 + (xi1 - xj + 6);
                        arow1[j] = sv1[jj] * scale + s_rel[r1 * NHEAD + h] + mrow1[j];
                    }
                }
            }
        }
    }
    __syncthreads();

    // ---- phase 3: softmax, one warp per (head, query-row) ----
    {
        const int warp = tid >> 5;
        const int lane = tid & 31;
        for (int row = warp; row < NHEAD * NTOK; row += TPB / 32) {
            float* a = &s_attn[row * 52];
            float v0 = (lane < NTOK)      ? a[lane]      : -1e30f;
            float v1 = (lane + 32 < NTOK) ? a[lane + 32] : -1e30f;
            float m = fmaxf(v0, v1);
            #pragma unroll
            for (int off = 16; off; off >>= 1)
                m = fmaxf(m, __shfl_xor_sync(0xffffffffu, m, off));
            float e0 = (lane < NTOK)      ? __expf(v0 - m) : 0.f;
            float e1 = (lane + 32 < NTOK) ? __expf(v1 - m) : 0.f;
            float ssum = e0 + e1;
            #pragma unroll
            for (int off = 16; off; off >>= 1)
                ssum += __shfl_xor_sync(0xffffffffu, ssum, off);
            const float inv = 1.0f / ssum;
            if (lane < NTOK)      a[lane]      = e0 * inv;
            if (lane + 32 < NTOK) a[lane + 32] = e1 * inv;
        }
    }
    __syncthreads();

    // ---- phase 4: attn @ v; thread = (row-pair, 4 adjacent c) ----
    for (int u = tid; u < 25 * 32; u += TPB) {
        const int ib = u >> 5;
        const int cg = u & 31;
        const int c4 = cg * 4;
        const int h  = cg >> 3;
        const int i0 = ib;
        const bool has1 = (ib < 24);
        const int i1 = has1 ? ib + 25 : ib;

        const float* a0r = &s_attn[(h * NTOK + i0) * 52];
        const float* a1r = &s_attn[(h * NTOK + i1) * 52];
        const float* vr  = &s_v[c4];

        u64 o0a = 0ull, o0b = 0ull, o1a = 0ull, o1b = 0ull;
        #pragma unroll 7
        for (int j = 0; j < NTOK; ++j) {
            const ulonglong2 vv = *reinterpret_cast<const ulonglong2*>(&vr[j * 128]);
            const float av0 = a0r[j];
            const float av1 = a1r[j];
            const u64 a0p = pack2(av0, av0);
            const u64 a1p = pack2(av1, av1);
            fma2(o0a, vv.x, a0p); fma2(o0b, vv.y, a0p);
            fma2(o1a, vv.x, a1p); fma2(o1b, vv.y, a1p);
        }
        const float2 f0a = unpack2(o0a), f0b = unpack2(o0b);
        float4 w0; w0.x = f0a.x; w0.y = f0a.y; w0.z = f0b.x; w0.w = f0b.y;
        *reinterpret_cast<float4*>(&s_o[i0 * 128 + c4]) = w0;
        if (has1) {
            const float2 f1a = unpack2(o1a), f1b = unpack2(o1b);
            float4 w1; w1.x = f1a.x; w1.y = f1a.y; w1.z = f1b.x; w1.w = f1b.y;
            *reinterpret_cast<float4*>(&s_o[i1 * 128 + c4]) = w1;
        }
    }
    __syncthreads();

    // ---- phase 5: output projection, smem-staged weights (4 chunks of 32 k) ----
    {
        // preload chunk 0: 32*128 = 4096 floats = 1024 float4
        {
            const float4* src = reinterpret_cast<const float4*>(proj_w);
            float4* dst = reinterpret_cast<float4*>(s_w);
            dst[tid]       = src[tid];
            dst[tid + 512] = src[tid + 512];
        }
        __syncthreads();

        u64 acc[13];
        #pragma unroll
        for (int i = 0; i < 13; ++i) acc[i] = 0ull;

        #pragma unroll 1
        for (int c = 0; c < 4; ++c) {
            float4 pf0, pf1;
            {
                const int cn = (c < 3) ? c + 1 : 3;
                const float4* src = reinterpret_cast<const float4*>(proj_w + (size_t)cn * 32 * 128);
                pf0 = src[tid];
                pf1 = src[tid + 512];
            }
            const float* wb = s_w + (c & 1) * 4096;
            #pragma unroll
            for (int t4 = 0; t4 < 8; ++t4) {
                const int kk = t4 * 4;
                const float w0 = wb[(kk + 0) * 128 + col];
                const float w1 = wb[(kk + 1) * 128 + col];
                const float w2 = wb[(kk + 2) * 128 + col];
                const float w3 = wb[(kk + 3) * 128 + col];
                const u64 w01 = pack2(w0, w1);
                const u64 w23 = pack2(w2, w3);
                const int kg = c * 32 + kk;
                #pragma unroll
                for (int i = 0; i < 13; ++i) {
                    const ulonglong2 ov = *reinterpret_cast<const ulonglong2*>(&s_o[(rbase + i) * 128 + kg]);
                    fma2(acc[i], ov.x, w01);
                    fma2(acc[i], ov.y, w23);
                }
            }
            {
                float4* dst = reinterpret_cast<float4*>(s_w + ((c + 1) & 1) * 4096);
                dst[tid]       = pf0;
                dst[tid + 512] = pf1;
            }
            __syncthreads();
        }
        const float bv = __ldg(&proj_b[col]);
        float* o = out + (size_t)blk * (NTOK * CDIM);
        for (int i = 0; i < rcnt; ++i) {
            const float2 f = unpack2(acc[i]);
            o[(rbase + i) * 128 + col] = f.x + f.y + bv;
        }
    }
}

extern "C" void kernel_launch(void* const* d_in, const int* in_sizes, int n_in,
                              void* d_out, int out_size)
{
    const float* x      = (const float*)d_in[0];
    const float* mask   = (const float*)d_in[1];
    const float* qkv_w  = (const float*)d_in[2];
    const float* qkv_b  = (const float*)d_in[3];
    const float* proj_w = (const float*)d_in[4];
    const float* proj_b = (const float*)d_in[5];
    const float* rel    = (const float*)d_in[6];
    float* out = (float*)d_out;

    cudaFuncSetAttribute(swin_window_attn_kernel,
                         cudaFuncAttributeMaxDynamicSharedMemorySize, SMEM_BYTES);
    swin_window_attn_kernel<<<2048, TPB, SMEM_BYTES>>>(
        x, mask, qkv_w, qkv_b, proj_w, proj_b, rel, out);
}

// round 9
// speedup vs baseline: 1.0553x; 1.0553x over previous
#include <cuda_runtime.h>

// Swin window attention, fused per-window kernel, v7:
// v5 with wider prefetch stages (P1: 4 k-steps, P5: 8 k-steps), register-resident,
// statically indexed. No added barriers (lesson from v6).
// B=32, nW=64 -> 2048 windows; N=49 tokens, C=128, H=4 heads, hd=32.

#define NWIN 64
#define NTOK 49
#define CDIM 128
#define NHEAD 4
#define HDIM 32
#define TPB 512
#define QPITCH 130

using u64 = unsigned long long;

__device__ __forceinline__ void fma2(u64& d, u64 a, u64 b) {
    asm("fma.rn.f32x2 %0, %1, %2, %0;" : "+l"(d) : "l"(a), "l"(b));
}
__device__ __forceinline__ u64 pack2(float lo, float hi) {
    u64 r; asm("mov.b64 %0, {%1, %2};" : "=l"(r) : "f"(lo), "f"(hi)); return r;
}
__device__ __forceinline__ float2 unpack2(u64 v) {
    float2 r; asm("mov.b64 {%0, %1}, %2;" : "=f"(r.x), "=f"(r.y) : "l"(v)); return r;
}

// shared memory layout (floats)
static constexpr int OFF_XT   = 0;                       // [128][52]; later s_o [49][128]
static constexpr int OFF_Q    = OFF_XT + 128 * 52;       // 6656, [49][130]
static constexpr int OFF_KT   = 13028;                   // [128][52] (16B aligned)
static constexpr int OFF_V    = OFF_KT + 128 * 52;       // 19684, [49][128]
static constexpr int OFF_ATTN = OFF_V + NTOK * CDIM;     // 25956, [196][52]
static constexpr int OFF_REL  = OFF_ATTN + (NHEAD * NTOK) * 52;  // 36148, 169*4
static constexpr int OFF_MASK = OFF_REL + 169 * NHEAD;   // 36824, 49*49
static constexpr int SMEM_FLOATS = OFF_MASK + NTOK * NTOK + 3;   // 39228
static constexpr int SMEM_BYTES  = SMEM_FLOATS * 4;      // 156912

// one k-step of the QKV GEMM body
#define P1_BODY(KK, W0, W1, W2)                                                    \
    {                                                                              \
        const float w0 = (W0), w1 = (W1), w2 = (W2);                               \
        const u64 w0p = pack2(w0, w0);                                             \
        const u64 w1p = pack2(w1, w1);                                             \
        const u64 w2p = pack2(w2, w2);                                             \
        const ulonglong2* xr = reinterpret_cast<const ulonglong2*>(&s_xT[(KK) * 52 + rbase]); \
        const ulonglong2 p01 = xr[0];                                              \
        const ulonglong2 p23 = xr[1];                                              \
        const ulonglong2 p45 = xr[2];                                              \
        const float x12 = s_xT[(KK) * 52 + rbase + 12];                            \
        fma2(a0[0], p01.x, w0p); fma2(a0[1], p01.y, w0p);                          \
        fma2(a0[2], p23.x, w0p); fma2(a0[3], p23.y, w0p);                          \
        fma2(a0[4], p45.x, w0p); fma2(a0[5], p45.y, w0p);                          \
        fma2(a1[0], p01.x, w1p); fma2(a1[1], p01.y, w1p);                          \
        fma2(a1[2], p23.x, w1p); fma2(a1[3], p23.y, w1p);                          \
        fma2(a1[4], p45.x, w1p); fma2(a1[5], p45.y, w1p);                          \
        fma2(a2[0], p01.x, w2p); fma2(a2[1], p01.y, w2p);                          \
        fma2(a2[2], p23.x, w2p); fma2(a2[3], p23.y, w2p);                          \
        fma2(a2[4], p45.x, w2p); fma2(a2[5], p45.y, w2p);                          \
        s0 += x12 * w0;  s1 += x12 * w1;  s2 += x12 * w2;                          \
    }

__global__ __launch_bounds__(TPB, 1)
void swin_window_attn_kernel(const float* __restrict__ x_all,
                             const float* __restrict__ mask,
                             const float* __restrict__ qkv_w,
                             const float* __restrict__ qkv_b,
                             const float* __restrict__ proj_w,
                             const float* __restrict__ proj_b,
                             const float* __restrict__ rel_table,
                             float* __restrict__ out)
{
    extern __shared__ float sm[];
    float* s_xT   = sm + OFF_XT;     // [128][52]
    float* s_q    = sm + OFF_Q;      // [49][130]
    float* s_kT   = sm + OFF_KT;     // [128][52]
    float* s_v    = sm + OFF_V;      // [49][128]
    float* s_attn = sm + OFF_ATTN;   // [196][52]
    float* s_rel  = sm + OFF_REL;    // [169][4]
    float* s_mask = sm + OFF_MASK;   // [49][49]
    float* s_o    = sm + OFF_XT;     // alias: x dead after phase 1

    const int tid = threadIdx.x;
    const int blk = blockIdx.x;
    const float* x  = x_all + (size_t)blk * (NTOK * CDIM);
    const float* mw = mask  + (size_t)(blk & (NWIN - 1)) * (NTOK * NTOK);

    // ---- stage x (transposed), rel_table, mask into smem ----
    for (int idx = tid; idx < NTOK * CDIM; idx += TPB) {
        const int r = idx >> 7;
        const int k = idx & 127;
        s_xT[k * 52 + r] = x[idx];
    }
    for (int idx = tid; idx < 169 * NHEAD; idx += TPB) s_rel[idx] = __ldg(&rel_table[idx]);
    for (int idx = tid; idx < NTOK * NTOK; idx += TPB) s_mask[idx] = __ldg(&mw[idx]);
    __syncthreads();

    const int col   = tid & 127;
    const int g     = tid >> 7;       // 0..3
    const int rbase = g * 12;         // 0,12,24,36
    const int rcnt  = (g == 3) ? 13 : 12;

    // ---- phase 1: QKV GEMM, f32x2, 4-k-step register double-buffered prefetch ----
    {
        u64 a0[6], a1[6], a2[6];
        float s0 = 0.f, s1 = 0.f, s2 = 0.f;
        #pragma unroll
        for (int p = 0; p < 6; ++p) { a0[p] = 0ull; a1[p] = 0ull; a2[p] = 0ull; }

        const float* wq = qkv_w + col;   // row stride 384

        float WA[12], WB[12];            // [k-in-stage*3 + chunk], all statically indexed

        // preload stage A (k = 0..3)
        #pragma unroll
        for (int t = 0; t < 4; ++t) {
            const float* r = wq + (size_t)t * 384;
            WA[t * 3 + 0] = __ldg(&r[0]);
            WA[t * 3 + 1] = __ldg(&r[128]);
            WA[t * 3 + 2] = __ldg(&r[256]);
        }

        #pragma unroll 1
        for (int k8 = 0; k8 < 128; k8 += 8) {
            // prefetch stage B (k = k8+4..k8+7); always in range
            #pragma unroll
            for (int t = 0; t < 4; ++t) {
                const float* r = wq + (size_t)(k8 + 4 + t) * 384;
                WB[t * 3 + 0] = __ldg(&r[0]);
                WB[t * 3 + 1] = __ldg(&r[128]);
                WB[t * 3 + 2] = __ldg(&r[256]);
            }
            // compute stage A (k = k8..k8+3)
            #pragma unroll
            for (int t = 0; t < 4; ++t)
                P1_BODY(k8 + t, WA[t * 3 + 0], WA[t * 3 + 1], WA[t * 3 + 2]);
            // prefetch stage A (k = k8+8..k8+11), clamped on final iteration
            #pragma unroll
            for (int t = 0; t < 4; ++t) {
                const int kn = (k8 + 8 + t < 128) ? (k8 + 8 + t) : (120 + t);
                const float* r = wq + (size_t)kn * 384;
                WA[t * 3 + 0] = __ldg(&r[0]);
                WA[t * 3 + 1] = __ldg(&r[128]);
                WA[t * 3 + 2] = __ldg(&r[256]);
            }
            // compute stage B (k = k8+4..k8+7)
            #pragma unroll
            for (int t = 0; t < 4; ++t)
                P1_BODY(k8 + 4 + t, WB[t * 3 + 0], WB[t * 3 + 1], WB[t * 3 + 2]);
        }

        const float b0 = __ldg(&qkv_b[col]);
        const float b1 = __ldg(&qkv_b[128 + col]);
        const float b2 = __ldg(&qkv_b[256 + col]);
        #pragma unroll
        for (int p = 0; p < 6; ++p) {
            const int r = rbase + 2 * p;
            const float2 f0 = unpack2(a0[p]);
            const float2 f1 = unpack2(a1[p]);
            const float2 f2 = unpack2(a2[p]);
            s_q[r * QPITCH + col]       = f0.x + b0;
            s_q[(r + 1) * QPITCH + col] = f0.y + b0;
            s_kT[col * 52 + r]          = f1.x + b1;
            s_kT[col * 52 + r + 1]      = f1.y + b1;
            s_v[r * 128 + col]          = f2.x + b2;
            s_v[(r + 1) * 128 + col]    = f2.y + b2;
        }
        if (rcnt == 13) {
            const int r = rbase + 12;
            s_q[r * QPITCH + col] = s0 + b0;
            s_kT[col * 52 + r]    = s1 + b1;
            s_v[r * 128 + col]    = s2 + b2;
        }
    }
    __syncthreads();

    // ---- phase 2: scores + bias + mask; thread = (h, row-pair, 4 adjacent j) ----
    {
        const float scale = 0.17677669529663687f;   // 1/sqrt(32)
        for (int u = tid; u < NHEAD * 25 * 13; u += TPB) {
            const int h   = u / (25 * 13);
            const int rem = u - h * (25 * 13);
            const int ib  = rem / 13;
            const int jg  = rem - ib * 13;
            const int j4  = jg * 4;
            const int i0  = ib;
            const bool has1 = (ib < 24);
            const int i1  = has1 ? ib + 25 : ib;

            const float* q0 = &s_q[i0 * QPITCH + h * HDIM];
            const float* q1 = &s_q[i1 * QPITCH + h * HDIM];
            const float* kc = &s_kT[(h * HDIM) * 52 + j4];

            u64 acc0a = 0ull, acc0b = 0ull, acc1a = 0ull, acc1b = 0ull;
            #pragma unroll
            for (int d = 0; d < HDIM; ++d) {
                const ulonglong2 kv = *reinterpret_cast<const ulonglong2*>(&kc[d * 52]);
                const float qv0 = q0[d];
                const float qv1 = q1[d];
                const u64 q0p = pack2(qv0, qv0);
                const u64 q1p = pack2(qv1, qv1);
                fma2(acc0a, kv.x, q0p); fma2(acc0b, kv.y, q0p);
                fma2(acc1a, kv.x, q1p); fma2(acc1b, kv.y, q1p);
            }
            const float2 r0a = unpack2(acc0a), r0b = unpack2(acc0b);
            const float2 r1a = unpack2(acc1a), r1b = unpack2(acc1b);
            float sv0[4] = {r0a.x, r0a.y, r0b.x, r0b.y};
            float sv1[4] = {r1a.x, r1a.y, r1b.x, r1b.y};

            const int yi0 = i0 / 7, xi0 = i0 - yi0 * 7;
            const int yi1 = i1 / 7, xi1 = i1 - yi1 * 7;
            float* arow0 = &s_attn[(h * NTOK + i0) * 52];
            float* arow1 = &s_attn[(h * NTOK + i1) * 52];
            const float* mrow0 = &s_mask[i0 * NTOK];
            const float* mrow1 = &s_mask[i1 * NTOK];
            #pragma unroll
            for (int jj = 0; jj < 4; ++jj) {
                const int j = j4 + jj;
                if (j < NTOK) {
                    const int yj = j / 7, xj = j - yj * 7;
                    const int r0 = (yi0 - yj + 6) * 13 + (xi0 - xj + 6);
                    arow0[j] = sv0[jj] * scale + s_rel[r0 * NHEAD + h] + mrow0[j];
                    if (has1) {
                        const int r1 = (yi1 - yj + 6) * 13 + (xi1 - xj + 6);
                        arow1[j] = sv1[jj] * scale + s_rel[r1 * NHEAD + h] + mrow1[j];
                    }
                }
            }
        }
    }
    __syncthreads();

    // ---- phase 3: softmax, one warp per (head, query-row) ----
    {
        const int warp = tid >> 5;
        const int lane = tid & 31;
        for (int row = warp; row < NHEAD * NTOK; row += TPB / 32) {
            float* a = &s_attn[row * 52];
            float v0 = (lane < NTOK)      ? a[lane]      : -1e30f;
            float v1 = (lane + 32 < NTOK) ? a[lane + 32] : -1e30f;
            float m = fmaxf(v0, v1);
            #pragma unroll
            for (int off = 16; off; off >>= 1)
                m = fmaxf(m, __shfl_xor_sync(0xffffffffu, m, off));
            float e0 = (lane < NTOK)      ? __expf(v0 - m) : 0.f;
            float e1 = (lane + 32 < NTOK) ? __expf(v1 - m) : 0.f;
            float ssum = e0 + e1;
            #pragma unroll
            for (int off = 16; off; off >>= 1)
                ssum += __shfl_xor_sync(0xffffffffu, ssum, off);
            const float inv = 1.0f / ssum;
            if (lane < NTOK)      a[lane]      = e0 * inv;
            if (lane + 32 < NTOK) a[lane + 32] = e1 * inv;
        }
    }
    __syncthreads();

    // ---- phase 4: attn @ v; thread = (row-pair, 4 adjacent c) ----
    for (int u = tid; u < 25 * 32; u += TPB) {
        const int ib = u >> 5;
        const int cg = u & 31;
        const int c4 = cg * 4;
        const int h  = cg >> 3;
        const int i0 = ib;
        const bool has1 = (ib < 24);
        const int i1 = has1 ? ib + 25 : ib;

        const float* a0r = &s_attn[(h * NTOK + i0) * 52];
        const float* a1r = &s_attn[(h * NTOK + i1) * 52];
        const float* vr  = &s_v[c4];

        u64 o0a = 0ull, o0b = 0ull, o1a = 0ull, o1b = 0ull;
        #pragma unroll 7
        for (int j = 0; j < NTOK; ++j) {
            const ulonglong2 vv = *reinterpret_cast<const ulonglong2*>(&vr[j * 128]);
            const float av0 = a0r[j];
            const float av1 = a1r[j];
            const u64 a0p = pack2(av0, av0);
            const u64 a1p = pack2(av1, av1);
            fma2(o0a, vv.x, a0p); fma2(o0b, vv.y, a0p);
            fma2(o1a, vv.x, a1p); fma2(o1b, vv.y, a1p);
        }
        const float2 f0a = unpack2(o0a), f0b = unpack2(o0b);
        float4 w0; w0.x = f0a.x; w0.y = f0a.y; w0.z = f0b.x; w0.w = f0b.y;
        *reinterpret_cast<float4*>(&s_o[i0 * 128 + c4]) = w0;
        if (has1) {
            const float2 f1a = unpack2(o1a), f1b = unpack2(o1b);
            float4 w1; w1.x = f1a.x; w1.y = f1a.y; w1.z = f1b.x; w1.w = f1b.y;
            *reinterpret_cast<float4*>(&s_o[i1 * 128 + c4]) = w1;
        }
    }
    __syncthreads();

    // ---- phase 5: output projection, f32x2, 8-k-step register double-buffered ----
    {
        u64 acc[13];
        #pragma unroll
        for (int i = 0; i < 13; ++i) acc[i] = 0ull;

        const float* wp = proj_w + col;   // row stride 128

        float WA[8], WB[8];

        // preload stage A (k = 0..7)
        #pragma unroll
        for (int t = 0; t < 8; ++t) WA[t] = __ldg(&wp[(size_t)t * 128]);

        #pragma unroll 1
        for (int k16 = 0; k16 < 128; k16 += 16) {
            // prefetch stage B (k = k16+8..k16+15); always in range
            #pragma unroll
            for (int t = 0; t < 8; ++t) WB[t] = __ldg(&wp[(size_t)(k16 + 8 + t) * 128]);
            // compute stage A (k = k16..k16+7), two 4-k blocks
            #pragma unroll
            for (int b = 0; b < 2; ++b) {
                const int kk = k16 + b * 4;
                const u64 w01 = pack2(WA[b * 4 + 0], WA[b * 4 + 1]);
                const u64 w23 = pack2(WA[b * 4 + 2], WA[b * 4 + 3]);
                #pragma unroll
                for (int i = 0; i < 13; ++i) {
                    const ulonglong2 ov = *reinterpret_cast<const ulonglong2*>(&s_o[(rbase + i) * 128 + kk]);
                    fma2(acc[i], ov.x, w01);
                    fma2(acc[i], ov.y, w23);
                }
            }
            // prefetch stage A (k = k16+16..k16+23), clamped on final iteration
            #pragma unroll
            for (int t = 0; t < 8; ++t) {
                const int kn = (k16 + 16 + t < 128) ? (k16 + 16 + t) : (120 + t);
                WA[t] = __ldg(&wp[(size_t)kn * 128]);
            }
            // compute stage B (k = k16+8..k16+15)
            #pragma unroll
            for (int b = 0; b < 2; ++b) {
                const int kk = k16 + 8 + b * 4;
                const u64 w01 = pack2(WB[b * 4 + 0], WB[b * 4 + 1]);
                const u64 w23 = pack2(WB[b * 4 + 2], WB[b * 4 + 3]);
                #pragma unroll
                for (int i = 0; i < 13; ++i) {
                    const ulonglong2 ov = *reinterpret_cast<const ulonglong2*>(&s_o[(rbase + i) * 128 + kk]);
                    fma2(acc[i], ov.x, w01);
                    fma2(acc[i], ov.y, w23);
                }
            }
        }
        const float bv = __ldg(&proj_b[col]);
        float* o = out + (size_t)blk * (NTOK * CDIM);
        for (int i = 0; i < rcnt; ++i) {
            const float2 f = unpack2(acc[i]);
            o[(rbase + i) * 128 + col] = f.x + f.y + bv;
        }
    }
}

extern "C" void kernel_launch(void* const* d_in, const int* in_sizes, int n_in,
                              void* d_out, int out_size)
{
    const float* x      = (const float*)d_in[0];
    const float* mask   = (const float*)d_in[1];
    const float* qkv_w  = (const float*)d_in[2];
    const float* qkv_b  = (const float*)d_in[3];
    const float* proj_w = (const float*)d_in[4];
    const float* proj_b = (const float*)d_in[5];
    const float* rel    = (const float*)d_in[6];
    float* out = (float*)d_out;

    cudaFuncSetAttribute(swin_window_attn_kernel,
                         cudaFuncAttributeMaxDynamicSharedMemorySize, SMEM_BYTES);
    swin_window_attn_kernel<<<2048, TPB, SMEM_BYTES>>>(
        x, mask, qkv_w, qkv_b, proj_w, proj_b, rel, out);
}

// round 11
// speedup vs baseline: 1.3561x; 1.2850x over previous
#include <cuda_runtime.h>

// Swin window attention, v8 (re-bench after infra failure): 3-kernel decomposition.
// K1: QKV GEMM [100352,128]@[128,384] -> per-head scratch q/k/v
// K2: per-(window,head) attention (scores+softmax+AV) -> o scratch
// K3: proj GEMM [100352,128]@[128,128] -> out
// B=32, nW=64 -> 2048 windows; N=49 tokens, C=128, H=4 heads, hd=32.

#define NWIN_TOT 2048
#define NTOK 49
#define CDIM 128
#define NHEAD 4
#define HDIM 32

using u64 = unsigned long long;

__device__ __forceinline__ void fma2(u64& d, u64 a, u64 b) {
    asm("fma.rn.f32x2 %0, %1, %2, %0;" : "+l"(d) : "l"(a), "l"(b));
}
__device__ __forceinline__ u64 pack2(float lo, float hi) {
    u64 r; asm("mov.b64 %0, {%1, %2};" : "=l"(r) : "f"(lo), "f"(hi)); return r;
}
__device__ __forceinline__ float2 unpack2(u64 v) {
    float2 r; asm("mov.b64 {%0, %1}, %2;" : "=f"(r.x), "=f"(r.y) : "l"(v)); return r;
}

// scratch: q/k/v per (window, head): [2048][4][49][32]; o: [2048*49][128]
static constexpr size_t QKV_ELEMS = (size_t)NWIN_TOT * NHEAD * NTOK * HDIM;  // 12,845,056
static constexpr size_t O_ELEMS   = (size_t)NWIN_TOT * NTOK * CDIM;          // 12,845,056
__device__ float g_q[QKV_ELEMS];
__device__ float g_k[QKV_ELEMS];
__device__ float g_v[QKV_ELEMS];
__device__ float g_o[O_ELEMS];

// ============================================================================
// GEMM kernel: C[M,N] = A[M,128] @ W[128,N] + bias, M=100352.
// CTA tile 128x128, 256 threads, thread tile 8x8 (f32x2 accumulators).
// mode 0: A = A_in (x), scatter epilogue to g_q/g_k/g_v (blockIdx.y = chunk)
// mode 1: A = g_o, direct epilogue to outp.
// ============================================================================
__global__ __launch_bounds__(256, 2)
void gemm128(const float* __restrict__ A_in,
             const float* __restrict__ W,
             const float* __restrict__ bias,
             int wstride, int mode, float* __restrict__ outp)
{
    __shared__ __align__(16) float s_a[2][16 * 132];
    __shared__ __align__(16) float s_b[2][16 * 128];

    const float* A = (mode == 0) ? A_in : g_o;
    const int tid = threadIdx.x;
    const int m0 = blockIdx.x * 128;
    const int n0 = blockIdx.y * 128;
    const int tm = tid >> 4;       // 0..15
    const int tn = tid & 15;       // 0..15

    u64 acc[8][4];
    #pragma unroll
    for (int i = 0; i < 8; ++i)
        #pragma unroll
        for (int j = 0; j < 4; ++j) acc[i][j] = 0ull;

    float4 pa[2], pb[2];
    // prologue: LDG + STS chunk 0
    #pragma unroll
    for (int r = 0; r < 2; ++r) {
        const int f = tid + 256 * r;
        pa[r] = *(const float4*)(A + (size_t)(m0 + (f >> 2)) * 128 + (f & 3) * 4);
        pb[r] = *(const float4*)(W + (size_t)(f >> 5) * wstride + n0 + (f & 31) * 4);
    }
    #pragma unroll
    for (int r = 0; r < 2; ++r) {
        const int f = tid + 256 * r;
        const int ml = f >> 2, kq = f & 3;
        s_a[0][(kq * 4 + 0) * 132 + ml] = pa[r].x;
        s_a[0][(kq * 4 + 1) * 132 + ml] = pa[r].y;
        s_a[0][(kq * 4 + 2) * 132 + ml] = pa[r].z;
        s_a[0][(kq * 4 + 3) * 132 + ml] = pa[r].w;
        *(float4*)&s_b[0][(f >> 5) * 128 + (f & 31) * 4] = pb[r];
    }
    __syncthreads();

    #pragma unroll 1
    for (int c = 0; c < 8; ++c) {
        const int buf = c & 1;
        if (c < 7) {
            const int k0 = (c + 1) * 16;
            #pragma unroll
            for (int r = 0; r < 2; ++r) {
                const int f = tid + 256 * r;
                pa[r] = *(const float4*)(A + (size_t)(m0 + (f >> 2)) * 128 + k0 + (f & 3) * 4);
                pb[r] = *(const float4*)(W + (size_t)(k0 + (f >> 5)) * wstride + n0 + (f & 31) * 4);
            }
        }
        // compute current chunk from smem (covers the LDG latency above)
        #pragma unroll
        for (int k = 0; k < 16; ++k) {
            const float4 a0 = *(const float4*)&s_a[buf][k * 132 + tm * 8];
            const float4 a1 = *(const float4*)&s_a[buf][k * 132 + tm * 8 + 4];
            const ulonglong2 b0 = *(const ulonglong2*)&s_b[buf][k * 128 + tn * 8];
            const ulonglong2 b1 = *(const ulonglong2*)&s_b[buf][k * 128 + tn * 8 + 4];
            const float av[8] = {a0.x, a0.y, a0.z, a0.w, a1.x, a1.y, a1.z, a1.w};
            #pragma unroll
            for (int i = 0; i < 8; ++i) {
                const u64 ap = pack2(av[i], av[i]);
                fma2(acc[i][0], b0.x, ap);
                fma2(acc[i][1], b0.y, ap);
                fma2(acc[i][2], b1.x, ap);
                fma2(acc[i][3], b1.y, ap);
            }
        }
        if (c < 7) {
            const int nbuf = buf ^ 1;
            #pragma unroll
            for (int r = 0; r < 2; ++r) {
                const int f = tid + 256 * r;
                const int ml = f >> 2, kq = f & 3;
                s_a[nbuf][(kq * 4 + 0) * 132 + ml] = pa[r].x;
                s_a[nbuf][(kq * 4 + 1) * 132 + ml] = pa[r].y;
                s_a[nbuf][(kq * 4 + 2) * 132 + ml] = pa[r].z;
                s_a[nbuf][(kq * 4 + 3) * 132 + ml] = pa[r].w;
                *(float4*)&s_b[nbuf][(f >> 5) * 128 + (f & 31) * 4] = pb[r];
            }
        }
        __syncthreads();
    }

    // epilogue
    float bv[8];
    #pragma unroll
    for (int j = 0; j < 8; ++j) bv[j] = __ldg(&bias[n0 + tn * 8 + j]);

    #pragma unroll
    for (int i = 0; i < 8; ++i) {
        const int m = m0 + tm * 8 + i;
        float r[8];
        #pragma unroll
        for (int j2 = 0; j2 < 4; ++j2) {
            const float2 f = unpack2(acc[i][j2]);
            r[j2 * 2]     = f.x + bv[j2 * 2];
            r[j2 * 2 + 1] = f.y + bv[j2 * 2 + 1];
        }
        const float4 v0 = make_float4(r[0], r[1], r[2], r[3]);
        const float4 v1 = make_float4(r[4], r[5], r[6], r[7]);
        if (mode == 0) {
            const int wi = m / NTOK;
            const int t  = m - wi * NTOK;
            const int h  = tn >> 2;              // head within 128-col chunk
            const int d0 = (tn & 3) * 8;         // dim offset within head
            float* dst = (blockIdx.y == 0) ? g_q : (blockIdx.y == 1) ? g_k : g_v;
            float* p = dst + (((size_t)(wi * NHEAD + h)) * NTOK + t) * HDIM + d0;
            *(float4*)p = v0;
            *(float4*)(p + 4) = v1;
        } else {
            float* p = outp + (size_t)m * 128 + n0 + tn * 8;
            *(float4*)p = v0;
            *(float4*)(p + 4) = v1;
        }
    }
}

// ============================================================================
// Attention kernel: one CTA per (window, head). 128 threads, ~30 KB smem.
// ============================================================================
__global__ __launch_bounds__(128)
void attn_kernel(const float* __restrict__ mask,
                 const float* __restrict__ rel_table)
{
    __shared__ __align__(16) float s_q[NTOK * 33];     // [49][33]
    __shared__ __align__(16) float s_kT[HDIM * 52];    // [32][52]
    __shared__ __align__(16) float s_v[NTOK * HDIM];   // [49][32]
    __shared__ __align__(16) float s_attn[NTOK * 52];  // [49][52]
    __shared__ float s_rel[172];

    const int tid = threadIdx.x;
    const int w = blockIdx.x >> 2;
    const int h = blockIdx.x & 3;
    const size_t base = ((size_t)(w * NHEAD + h)) * NTOK * HDIM;
    const float* qg = g_q + base;
    const float* kg = g_k + base;
    const float* vg = g_v + base;
    const float* mw = mask + (size_t)(w & 63) * (NTOK * NTOK);

    for (int idx = tid; idx < NTOK * HDIM; idx += 128) {
        const int t = idx >> 5, d = idx & 31;
        const float kvv = kg[idx];
        s_q[t * 33 + d]  = qg[idx];
        s_kT[d * 52 + t] = kvv;
        s_v[idx]         = vg[idx];
    }
    for (int idx = tid; idx < 169; idx += 128) s_rel[idx] = __ldg(&rel_table[idx * NHEAD + h]);
    __syncthreads();

    // ---- scores + bias + mask; thread = (row-pair, 4 adjacent j) ----
    const float scale = 0.17677669529663687f;   // 1/sqrt(32)
    for (int u = tid; u < 25 * 13; u += 128) {
        const int ib = u / 13;
        const int jg = u - ib * 13;
        const int j4 = jg * 4;
        const int i0 = ib;
        const bool has1 = (ib < 24);
        const int i1 = has1 ? ib + 25 : ib;

        const float* q0 = s_q + i0 * 33;
        const float* q1 = s_q + i1 * 33;
        const float* kc = s_kT + j4;

        u64 acc0a = 0ull, acc0b = 0ull, acc1a = 0ull, acc1b = 0ull;
        #pragma unroll
        for (int d = 0; d < HDIM; ++d) {
            const ulonglong2 kv = *(const ulonglong2*)(kc + d * 52);
            const float qv0 = q0[d];
            const float qv1 = q1[d];
            const u64 q0p = pack2(qv0, qv0);
            const u64 q1p = pack2(qv1, qv1);
            fma2(acc0a, kv.x, q0p); fma2(acc0b, kv.y, q0p);
            fma2(acc1a, kv.x, q1p); fma2(acc1b, kv.y, q1p);
        }
        const float2 r0a = unpack2(acc0a), r0b = unpack2(acc0b);
        const float2 r1a = unpack2(acc1a), r1b = unpack2(acc1b);
        const float sv0[4] = {r0a.x, r0a.y, r0b.x, r0b.y};
        const float sv1[4] = {r1a.x, r1a.y, r1b.x, r1b.y};

        const int yi0 = i0 / 7, xi0 = i0 - yi0 * 7;
        const int yi1 = i1 / 7, xi1 = i1 - yi1 * 7;
        #pragma unroll
        for (int jj = 0; jj < 4; ++jj) {
            const int j = j4 + jj;
            if (j < NTOK) {
                const int yj = j / 7, xj = j - yj * 7;
                const int r0 = (yi0 - yj + 6) * 13 + (xi0 - xj + 6);
                s_attn[i0 * 52 + j] = sv0[jj] * scale + s_rel[r0] + __ldg(&mw[i0 * NTOK + j]);
                if (has1) {
                    const int r1 = (yi1 - yj + 6) * 13 + (xi1 - xj + 6);
                    s_attn[i1 * 52 + j] = sv1[jj] * scale + s_rel[r1] + __ldg(&mw[i1 * NTOK + j]);
                }
            }
        }
    }
    __syncthreads();

    // ---- softmax: one warp per query-row ----
    {
        const int warp = tid >> 5;
        const int lane = tid & 31;
        for (int row = warp; row < NTOK; row += 4) {
            float* a = s_attn + row * 52;
            float v0 = (lane < NTOK)      ? a[lane]      : -1e30f;
            float v1 = (lane + 32 < NTOK) ? a[lane + 32] : -1e30f;
            float m = fmaxf(v0, v1);
            #pragma unroll
            for (int off = 16; off; off >>= 1)
                m = fmaxf(m, __shfl_xor_sync(0xffffffffu, m, off));
            float e0 = (lane < NTOK)      ? __expf(v0 - m) : 0.f;
            float e1 = (lane + 32 < NTOK) ? __expf(v1 - m) : 0.f;
            float ssum = e0 + e1;
            #pragma unroll
            for (int off = 16; off; off >>= 1)
                ssum += __shfl_xor_sync(0xffffffffu, ssum, off);
            const float inv = 1.0f / ssum;
            if (lane < NTOK)      a[lane]      = e0 * inv;
            if (lane + 32 < NTOK) a[lane + 32] = e1 * inv;
        }
    }
    __syncthreads();

    // ---- attn @ v -> g_o; thread = (row-pair, 4 adjacent dims) ----
    for (int u = tid; u < 25 * 8; u += 128) {
        const int ib = u >> 3;
        const int cg = u & 7;
        const int c4 = cg * 4;
        const int i0 = ib;
        const bool has1 = (ib < 24);
        const int i1 = has1 ? ib + 25 : ib;

        const float* a0r = s_attn + i0 * 52;
        const float* a1r = s_attn + i1 * 52;
        const float* vr  = s_v + c4;

        u64 o0a = 0ull, o0b = 0ull, o1a = 0ull, o1b = 0ull;
        #pragma unroll 7
        for (int j = 0; j < NTOK; ++j) {
            const ulonglong2 vv = *(const ulonglong2*)(vr + j * HDIM);
            const float av0 = a0r[j];
            const float av1 = a1r[j];
            const u64 a0p = pack2(av0, av0);
            const u64 a1p = pack2(av1, av1);
            fma2(o0a, vv.x, a0p); fma2(o0b, vv.y, a0p);
            fma2(o1a, vv.x, a1p); fma2(o1b, vv.y, a1p);
        }
        const float2 f0a = unpack2(o0a), f0b = unpack2(o0b);
        *(float4*)(g_o + ((size_t)w * NTOK + i0) * CDIM + h * HDIM + c4) =
            make_float4(f0a.x, f0a.y, f0b.x, f0b.y);
        if (has1) {
            const float2 f1a = unpack2(o1a), f1b = unpack2(o1b);
            *(float4*)(g_o + ((size_t)w * NTOK + i1) * CDIM + h * HDIM + c4) =
                make_float4(f1a.x, f1a.y, f1b.x, f1b.y);
        }
    }
}

extern "C" void kernel_launch(void* const* d_in, const int* in_sizes, int n_in,
                              void* d_out, int out_size)
{
    const float* x      = (const float*)d_in[0];
    const float* mask   = (const float*)d_in[1];
    const float* qkv_w  = (const float*)d_in[2];
    const float* qkv_b  = (const float*)d_in[3];
    const float* proj_w = (const float*)d_in[4];
    const float* proj_b = (const float*)d_in[5];
    const float* rel    = (const float*)d_in[6];
    float* out = (float*)d_out;

    // K1: QKV GEMM -> g_q/g_k/g_v
    gemm128<<<dim3(784, 3), 256>>>(x, qkv_w, qkv_b, 384, 0, nullptr);
    // K2: attention -> g_o
    attn_kernel<<<NWIN_TOT * NHEAD, 128>>>(mask, rel);
    // K3: proj GEMM -> out
    gemm128<<<dim3(784, 1), 256>>>(x, proj_w, proj_b, 128, 1, out);
}